// round 8
// baseline (speedup 1.0000x reference)
#include <cuda_runtime.h>
#include <cuda_fp16.h>
#include <stdint.h>

// ============================================================================
// FibonacciKAN via monomial re-expansion, legacy mma.sync path (tcgen05 is
// unavailable: harness PTX targets compute_103, 'a'-gated ops rejected).
//   Y[32768,256] = A[32768,1024] @ W[1024,256] + bias, A = powers of tanh(x)
// R7: break the convoy -- register fragment double-buffering (LDSM for step
// s+1 overlaps MMAs of step s) + 3-stage cp.async W pipeline (wait_group 1).
// ============================================================================

#define B_ROWS 32768
#define IN_DIM 256
#define OUT_DIM 256
#define KDIM 1024
#define BM 128
#define BN 256
#define BK 64
#define NKT (KDIM / BK)       // 16
#define NTHREADS 512

#define SA 72                 // A row stride in halves (144 B)
#define SWROW 72              // W row stride in halves
#define ABYTES (BM * SA * 2)      // 18432
#define WBYTES (BN * SWROW * 2)   // 36864
#define SM_A0 0
#define SM_A1 (SM_A0 + ABYTES)
#define SM_W0 (SM_A1 + ABYTES)    // 3 W buffers
#define SM_TOTAL (SM_W0 + 3 * WBYTES)   // 147456 bytes

__device__ __half g_W[OUT_DIM * KDIM];   // [o][k], k-contiguous
__device__ float  g_bias[OUT_DIM];

// ---------------------------------------------------------------------------
__device__ __forceinline__ uint32_t smem_u32(const void* p) {
    uint32_t a;
    asm("{ .reg .u64 t; cvta.to.shared.u64 t, %1; cvt.u32.u64 %0, t; }"
        : "=r"(a) : "l"(p));
    return a;
}
__device__ __forceinline__ void cp_async16(uint32_t dst, const void* src) {
    asm volatile("cp.async.cg.shared.global [%0], [%1], 16;"
                 :: "r"(dst), "l"(src) : "memory");
}
__device__ __forceinline__ void cp_commit() {
    asm volatile("cp.async.commit_group;" ::: "memory");
}
template <int N>
__device__ __forceinline__ void cp_wait() {
    asm volatile("cp.async.wait_group %0;" :: "n"(N) : "memory");
}
__device__ __forceinline__ void ldsm_x4(uint32_t* r, uint32_t addr) {
    asm volatile("ldmatrix.sync.aligned.m8n8.x4.shared.b16 {%0,%1,%2,%3}, [%4];"
                 : "=r"(r[0]), "=r"(r[1]), "=r"(r[2]), "=r"(r[3]) : "r"(addr));
}
__device__ __forceinline__ uint32_t pack_h2(float a, float b) {
    __half2 h = __floats2half2_rn(a, b);
    return *(uint32_t*)&h;
}
__device__ __forceinline__ float tanh_fast(float x) {
    float y;
    asm("tanh.approx.f32 %0, %1;" : "=f"(y) : "f"(x));
    return y;
}

// ---------------------------------------------------------------------------
__global__ void prep_weights_kernel(const float* __restrict__ C) {
    int o = blockIdx.x;
    int i = threadIdx.x;
    const float* c = C + ((size_t)i * OUT_DIM + o) * 6;
    float c1 = c[1], c2 = c[2], c3 = c[3], c4 = c[4], c5 = c[5];
    __half2* dst = (__half2*)(g_W + (size_t)o * KDIM + i * 4);
    dst[0] = __floats2half2_rn(c2 + 2.0f * c4, c3 + 3.0f * c5);
    dst[1] = __floats2half2_rn(c4, c5);

    float v = c1 + c3 + c5;
    #pragma unroll
    for (int s = 16; s > 0; s >>= 1)
        v += __shfl_xor_sync(0xFFFFFFFF, v, s);
    __shared__ float sb[8];
    if ((i & 31) == 0) sb[i >> 5] = v;
    __syncthreads();
    if (i < 8) {
        float w = sb[i];
        #pragma unroll
        for (int s = 4; s > 0; s >>= 1)
            w += __shfl_xor_sync(0xFF, w, s);
        if (i == 0) g_bias[o] = w;
    }
}

// ---------------------------------------------------------------------------
__global__ __launch_bounds__(NTHREADS, 1)
void kan_gemm_kernel(const float* __restrict__ X, float* __restrict__ Y) {
    extern __shared__ char smem[];
    const uint32_t sbase = smem_u32(smem);
    const int tid  = threadIdx.x;
    const int warp = tid >> 5;
    const int lane = tid & 31;
    const int wr = warp >> 2;
    const int wc = warp & 3;
    const int g  = lane >> 2;
    const int tig = lane & 3;
    const int rowbase = blockIdx.x * BM;

    // A staging geometry
    const int arow = tid >> 2;
    const int agrp = tid & 3;
    const float* xptr = X + (size_t)(rowbase + arow) * IN_DIM + agrp * 4;
    const uint32_t ast = (uint32_t)arow * (SA * 2) + (uint32_t)agrp * 32;

    // W staging geometry
    const int wrow0 = tid >> 3;
    const int wseg  = tid & 7;

    // ldmatrix per-thread base offsets (bytes)
    const uint32_t a_lds = (uint32_t)(wr * 32 + (lane & 7) + ((lane >> 3) & 1) * 8)
                           * (SA * 2) + ((lane >> 4) & 1) * 16;
    const uint32_t b_lds = (uint32_t)(wc * 64 + (lane & 7) + ((lane >> 4) & 1) * 8)
                           * (SWROW * 2) + ((lane >> 3) & 1) * 16;

    float acc[2][8][4];
    #pragma unroll
    for (int mt = 0; mt < 2; ++mt)
        #pragma unroll
        for (int nt = 0; nt < 8; ++nt)
            #pragma unroll
            for (int q = 0; q < 4; ++q) acc[mt][nt][q] = 0.0f;

    // ---- prologue: W tiles 0 and 1 in flight; A tile 0 staged ----
    #pragma unroll
    for (int j = 0; j < 4; ++j) {
        int nrow = wrow0 + j * 64;
        cp_async16(sbase + SM_W0 + (uint32_t)nrow * (SWROW * 2) + wseg * 16,
                   g_W + (size_t)nrow * KDIM + wseg * 8);
    }
    cp_commit();
    #pragma unroll
    for (int j = 0; j < 4; ++j) {
        int nrow = wrow0 + j * 64;
        cp_async16(sbase + SM_W0 + WBYTES + (uint32_t)nrow * (SWROW * 2) + wseg * 16,
                   g_W + (size_t)nrow * KDIM + BK + wseg * 8);
    }
    cp_commit();
    {
        float4 xv = *(const float4*)xptr;
        float t0 = tanh_fast(xv.x), t1 = tanh_fast(xv.y);
        float t2 = tanh_fast(xv.z), t3 = tanh_fast(xv.w);
        float s0 = t0*t0, s1 = t1*t1, s2 = t2*t2, s3 = t3*t3;
        uint4 c01, c23;
        c01.x = pack_h2(t0, s0); c01.y = pack_h2(s0*t0, s0*s0);
        c01.z = pack_h2(t1, s1); c01.w = pack_h2(s1*t1, s1*s1);
        c23.x = pack_h2(t2, s2); c23.y = pack_h2(s2*t2, s2*s2);
        c23.z = pack_h2(t3, s3); c23.w = pack_h2(s3*t3, s3*s3);
        *(uint4*)(smem + SM_A0 + ast)      = c01;
        *(uint4*)(smem + SM_A0 + ast + 16) = c23;
    }

    for (int kt = 0; kt < NKT; ++kt) {
        const uint32_t Ab  = sbase + (kt & 1 ? SM_A1 : SM_A0);
        const uint32_t Abn = sbase + (kt & 1 ? SM_A0 : SM_A1);
        const uint32_t Wb  = sbase + SM_W0 + (kt % 3) * WBYTES;

        // X prefetch for next tile
        float4 xv;
        if (kt + 1 < NKT) xv = *(const float4*)(xptr + (kt + 1) * 16);

        cp_wait<1>();          // W tile kt landed (kt+1 may still be in flight)
        __syncthreads();       // A tile kt visible; A-nxt free; W buf kt+2%3 free

        // issue cp.async for W tile kt+2
        if (kt + 2 < NKT) {
            const uint32_t Wbn = sbase + SM_W0 + ((kt + 2) % 3) * WBYTES;
            #pragma unroll
            for (int j = 0; j < 4; ++j) {
                int nrow = wrow0 + j * 64;
                cp_async16(Wbn + (uint32_t)nrow * (SWROW * 2) + wseg * 16,
                           g_W + (size_t)nrow * KDIM + (kt + 2) * BK + wseg * 8);
            }
            cp_commit();
        } else {
            cp_commit();       // keep group count in sync for wait<1>
        }

        // ---- pipelined MMA: 16 steps (kk,ntp), frags prefetched one step ahead
        uint32_t afr[2][8];    // ping-pong by kk parity; [mt*4 + q]
        uint32_t bfr[2][4];    // ping-pong by step parity
        ldsm_x4(&afr[0][0], Ab + a_lds);
        ldsm_x4(&afr[0][4], Ab + a_lds + 16 * (SA * 2));
        ldsm_x4(bfr[0], Wb + b_lds);
        #pragma unroll
        for (int s = 0; s < 16; ++s) {
            const int kk  = s >> 2;
            const int ntp = s & 3;
            const int cb  = s & 1;
            const int ca  = kk & 1;
            if (s + 1 < 16) {
                const int nkk  = (s + 1) >> 2;
                const int nntp = (s + 1) & 3;
                if (nntp == 0) {
                    ldsm_x4(&afr[nkk & 1][0], Ab + a_lds + nkk * 32);
                    ldsm_x4(&afr[nkk & 1][4], Ab + a_lds + 16 * (SA * 2) + nkk * 32);
                }
                ldsm_x4(bfr[cb ^ 1],
                        Wb + b_lds + nntp * 16 * (SWROW * 2) + nkk * 32);
            }
            #pragma unroll
            for (int h = 0; h < 2; ++h) {
                const int nt = ntp * 2 + h;
                #pragma unroll
                for (int mt = 0; mt < 2; ++mt) {
                    asm volatile(
                        "mma.sync.aligned.m16n8k16.row.col.f32.f16.f16.f32 "
                        "{%0,%1,%2,%3}, {%4,%5,%6,%7}, {%8,%9}, {%0,%1,%2,%3};\n"
                        : "+f"(acc[mt][nt][0]), "+f"(acc[mt][nt][1]),
                          "+f"(acc[mt][nt][2]), "+f"(acc[mt][nt][3])
                        : "r"(afr[ca][mt * 4 + 0]), "r"(afr[ca][mt * 4 + 1]),
                          "r"(afr[ca][mt * 4 + 2]), "r"(afr[ca][mt * 4 + 3]),
                          "r"(bfr[cb][h * 2]), "r"(bfr[cb][h * 2 + 1]));
                }
            }
        }

        // ---- stage A tile kt+1 ----
        if (kt + 1 < NKT) {
            float t0 = tanh_fast(xv.x), t1 = tanh_fast(xv.y);
            float t2 = tanh_fast(xv.z), t3 = tanh_fast(xv.w);
            float s0 = t0*t0, s1 = t1*t1, s2 = t2*t2, s3 = t3*t3;
            uint4 c01, c23;
            c01.x = pack_h2(t0, s0); c01.y = pack_h2(s0*t0, s0*s0);
            c01.z = pack_h2(t1, s1); c01.w = pack_h2(s1*t1, s1*s1);
            c23.x = pack_h2(t2, s2); c23.y = pack_h2(s2*t2, s2*s2);
            c23.z = pack_h2(t3, s3); c23.w = pack_h2(s3*t3, s3*s3);
            *(uint4*)((char*)smem + (Abn - sbase) + ast)      = c01;
            *(uint4*)((char*)smem + (Abn - sbase) + ast + 16) = c23;
        }
    }

    // ---- epilogue: + bias, fp32 store ----
    #pragma unroll
    for (int mt = 0; mt < 2; ++mt) {
        int r0 = rowbase + wr * 32 + mt * 16;
        #pragma unroll
        for (int nt = 0; nt < 8; ++nt) {
            int c0 = wc * 64 + nt * 8 + tig * 2;
            float b0 = __ldg(&g_bias[c0]);
            float b1 = __ldg(&g_bias[c0 + 1]);
            int r = r0 + g;
            float2 lo = make_float2(acc[mt][nt][0] + b0, acc[mt][nt][1] + b1);
            float2 hi = make_float2(acc[mt][nt][2] + b0, acc[mt][nt][3] + b1);
            *(float2*)(Y + (size_t)r * OUT_DIM + c0)       = lo;
            *(float2*)(Y + (size_t)(r + 8) * OUT_DIM + c0) = hi;
        }
    }
}

// ---------------------------------------------------------------------------
extern "C" void kernel_launch(void* const* d_in, const int* in_sizes, int n_in,
                              void* d_out, int out_size) {
    const float* x = (const float*)d_in[0];
    const float* coeffs = (const float*)d_in[1];
    if (n_in >= 2 && in_sizes[0] == OUT_DIM * IN_DIM * 6) {
        coeffs = (const float*)d_in[0];
        x = (const float*)d_in[1];
    }
    float* y = (float*)d_out;

    static bool attr_set = false;
    if (!attr_set) {
        cudaFuncSetAttribute(kan_gemm_kernel,
                             cudaFuncAttributeMaxDynamicSharedMemorySize, SM_TOTAL);
        attr_set = true;
    }

    prep_weights_kernel<<<OUT_DIM, IN_DIM>>>(coeffs);
    kan_gemm_kernel<<<B_ROWS / BM, NTHREADS, SM_TOTAL>>>(x, y);
}

// round 9
// speedup vs baseline: 1.5791x; 1.5791x over previous
#include <cuda_runtime.h>
#include <cuda_fp16.h>
#include <stdint.h>

// ============================================================================
// FibonacciKAN via monomial re-expansion, legacy mma.sync path (tcgen05 is
// unavailable: harness PTX targets compute_103, 'a'-gated ops rejected).
//   Y[32768,256] = A[32768,1024] @ W[1024,256] + bias, A = powers of tanh(x)
// R8: occupancy play. Two 128x128 CTAs per SM (256 thr, launch_bounds(256,2))
// replace one 128x256 CTA. Hardware interleaving of the two CTAs overlaps one
// CTA's staging/barrier phase with the other's MMA phase. Mainloop reverted to
// the proven R6 (non-register-pipelined) shape after the R7 spill regression.
// ============================================================================

#define B_ROWS 32768
#define IN_DIM 256
#define OUT_DIM 256
#define KDIM 1024
#define BM 128
#define BN 128                // per-CTA output columns
#define BK 64
#define NKT (KDIM / BK)       // 16
#define NTHREADS 256

#define SA 72                 // A row stride in halves (144 B)
#define SWROW 72
#define ABYTES (BM * SA * 2)      // 18432
#define WBYTES (BN * SWROW * 2)   // 18432
#define SM_A0 0
#define SM_A1 (SM_A0 + ABYTES)
#define SM_W0 (SM_A1 + ABYTES)
#define SM_W1 (SM_W0 + WBYTES)
#define SM_TOTAL (SM_W1 + WBYTES)   // 73728 bytes/CTA -> 2 CTAs/SM

__device__ __half g_W[OUT_DIM * KDIM];   // [o][k], k-contiguous
__device__ float  g_bias[OUT_DIM];

// ---------------------------------------------------------------------------
__device__ __forceinline__ uint32_t smem_u32(const void* p) {
    uint32_t a;
    asm("{ .reg .u64 t; cvta.to.shared.u64 t, %1; cvt.u32.u64 %0, t; }"
        : "=r"(a) : "l"(p));
    return a;
}
__device__ __forceinline__ void cp_async16(uint32_t dst, const void* src) {
    asm volatile("cp.async.cg.shared.global [%0], [%1], 16;"
                 :: "r"(dst), "l"(src) : "memory");
}
__device__ __forceinline__ void cp_commit() {
    asm volatile("cp.async.commit_group;" ::: "memory");
}
__device__ __forceinline__ void cp_wait0() {
    asm volatile("cp.async.wait_group 0;" ::: "memory");
}
__device__ __forceinline__ void ldsm_x4(uint32_t& r0, uint32_t& r1,
                                        uint32_t& r2, uint32_t& r3, uint32_t addr) {
    asm volatile("ldmatrix.sync.aligned.m8n8.x4.shared.b16 {%0,%1,%2,%3}, [%4];"
                 : "=r"(r0), "=r"(r1), "=r"(r2), "=r"(r3) : "r"(addr));
}
__device__ __forceinline__ uint32_t pack_h2(float a, float b) {
    __half2 h = __floats2half2_rn(a, b);
    return *(uint32_t*)&h;
}
__device__ __forceinline__ float tanh_fast(float x) {
    float y;
    asm("tanh.approx.f32 %0, %1;" : "=f"(y) : "f"(x));
    return y;
}

// ---------------------------------------------------------------------------
// Weight prep: C[i][o][d] -> monomial W[o][k=i*4+p] fp16 + bias[o]
// ---------------------------------------------------------------------------
__global__ void prep_weights_kernel(const float* __restrict__ C) {
    int o = blockIdx.x;
    int i = threadIdx.x;
    const float* c = C + ((size_t)i * OUT_DIM + o) * 6;
    float c1 = c[1], c2 = c[2], c3 = c[3], c4 = c[4], c5 = c[5];
    __half2* dst = (__half2*)(g_W + (size_t)o * KDIM + i * 4);
    dst[0] = __floats2half2_rn(c2 + 2.0f * c4, c3 + 3.0f * c5);
    dst[1] = __floats2half2_rn(c4, c5);

    float v = c1 + c3 + c5;
    #pragma unroll
    for (int s = 16; s > 0; s >>= 1)
        v += __shfl_xor_sync(0xFFFFFFFF, v, s);
    __shared__ float sb[8];
    if ((i & 31) == 0) sb[i >> 5] = v;
    __syncthreads();
    if (i < 8) {
        float w = sb[i];
        #pragma unroll
        for (int s = 4; s > 0; s >>= 1)
            w += __shfl_xor_sync(0xFF, w, s);
        if (i == 0) g_bias[o] = w;
    }
}

// ---------------------------------------------------------------------------
// Fused pipelined GEMM: 128x128 per CTA, 2 CTAs/SM
// ---------------------------------------------------------------------------
__global__ __launch_bounds__(NTHREADS, 2)
void kan_gemm_kernel(const float* __restrict__ X, float* __restrict__ Y) {
    extern __shared__ char smem[];
    const uint32_t sbase = smem_u32(smem);
    const int tid  = threadIdx.x;
    const int warp = tid >> 5;          // 0..7
    const int lane = tid & 31;
    const int wr = warp >> 1;           // 0..3 (32-row warp tiles)
    const int wc = warp & 1;            // 0..1 (64-col warp tiles)
    const int g  = lane >> 2;
    const int tig = lane & 3;
    const int rowbase = (blockIdx.x >> 1) * BM;
    const int colbase = (blockIdx.x & 1) * BN;

    // A staging geometry: 512 slots (row, 4-ch group); 2 slots per thread
    const int arow0 = tid >> 1;                   // slot j: r = tid>>1 + j*... see loop
    // slot e = tid + j*256; r = e>>2; grp = e&3

    // W staging geometry: 1024 16B chunks, 4 per thread
    const int wrow0 = tid >> 3;         // 0..31 (+32 per j)
    const int wseg  = tid & 7;          // 0..7

    // ldmatrix per-thread base offsets (bytes)
    const uint32_t a_lds = (uint32_t)(wr * 32 + (lane & 7) + ((lane >> 3) & 1) * 8)
                           * (SA * 2) + ((lane >> 4) & 1) * 16;
    const uint32_t b_lds = (uint32_t)(wc * 64 + (lane & 7) + ((lane >> 4) & 1) * 8)
                           * (SWROW * 2) + ((lane >> 3) & 1) * 16;
    (void)arow0;

    float acc[2][8][4];
    #pragma unroll
    for (int mt = 0; mt < 2; ++mt)
        #pragma unroll
        for (int nt = 0; nt < 8; ++nt)
            #pragma unroll
            for (int q = 0; q < 4; ++q) acc[mt][nt][q] = 0.0f;

    // ---- prologue: stage tile 0 into buffer 0 ----
    {
        #pragma unroll
        for (int j = 0; j < 4; ++j) {
            int nrow = wrow0 + j * 32;                 // 0..127 (CTA-local col)
            cp_async16(sbase + SM_W0 + (uint32_t)nrow * (SWROW * 2) + wseg * 16,
                       g_W + (size_t)(colbase + nrow) * KDIM + wseg * 8);
        }
        cp_commit();
        #pragma unroll
        for (int j = 0; j < 2; ++j) {
            int e = tid + j * NTHREADS;                // 0..511
            int r = e >> 2;
            int grp = e & 3;
            float4 xv = *(const float4*)(X + (size_t)(rowbase + r) * IN_DIM + grp * 4);
            float t0 = tanh_fast(xv.x), t1 = tanh_fast(xv.y);
            float t2 = tanh_fast(xv.z), t3 = tanh_fast(xv.w);
            float s0 = t0*t0, s1 = t1*t1, s2 = t2*t2, s3 = t3*t3;
            uint4 c01, c23;
            c01.x = pack_h2(t0, s0); c01.y = pack_h2(s0*t0, s0*s0);
            c01.z = pack_h2(t1, s1); c01.w = pack_h2(s1*t1, s1*s1);
            c23.x = pack_h2(t2, s2); c23.y = pack_h2(s2*t2, s2*s2);
            c23.z = pack_h2(t3, s3); c23.w = pack_h2(s3*t3, s3*s3);
            uint32_t off = (uint32_t)r * (SA * 2) + (uint32_t)grp * 32;
            *(uint4*)(smem + SM_A0 + off)      = c01;
            *(uint4*)(smem + SM_A0 + off + 16) = c23;
        }
    }

    for (int kt = 0; kt < NKT; ++kt) {
        const int cur = kt & 1;
        const uint32_t Ab  = sbase + (cur ? SM_A1 : SM_A0);
        const uint32_t Wb  = sbase + (cur ? SM_W1 : SM_W0);
        const uint32_t Abn = sbase + (cur ? SM_A0 : SM_A1);
        const uint32_t Wbn = sbase + (cur ? SM_W0 : SM_W1);

        // X prefetch for next tile (2 slots per thread)
        float4 xv0, xv1;
        if (kt + 1 < NKT) {
            int e0 = tid, e1 = tid + NTHREADS;
            xv0 = *(const float4*)(X + (size_t)(rowbase + (e0 >> 2)) * IN_DIM
                                   + (kt + 1) * 16 + (e0 & 3) * 4);
            xv1 = *(const float4*)(X + (size_t)(rowbase + (e1 >> 2)) * IN_DIM
                                   + (kt + 1) * 16 + (e1 & 3) * 4);
        }

        cp_wait0();
        __syncthreads();

        // issue cp.async for W tile kt+1
        if (kt + 1 < NKT) {
            #pragma unroll
            for (int j = 0; j < 4; ++j) {
                int nrow = wrow0 + j * 32;
                cp_async16(Wbn + (uint32_t)nrow * (SWROW * 2) + wseg * 16,
                           g_W + (size_t)(colbase + nrow) * KDIM + (kt + 1) * BK + wseg * 8);
            }
            cp_commit();
        }

        // ---- MMAs on tile kt: 4 k-steps of 16 (R6-proven shape) ----
        #pragma unroll
        for (int kk = 0; kk < 4; ++kk) {
            uint32_t a[2][4];
            #pragma unroll
            for (int mt = 0; mt < 2; ++mt)
                ldsm_x4(a[mt][0], a[mt][1], a[mt][2], a[mt][3],
                        Ab + a_lds + mt * 16 * (SA * 2) + kk * 32);
            #pragma unroll
            for (int ntp = 0; ntp < 4; ++ntp) {
                uint32_t b[4];
                ldsm_x4(b[0], b[1], b[2], b[3],
                        Wb + b_lds + ntp * 16 * (SWROW * 2) + kk * 32);
                #pragma unroll
                for (int h = 0; h < 2; ++h) {
                    const int nt = ntp * 2 + h;
                    #pragma unroll
                    for (int mt = 0; mt < 2; ++mt) {
                        asm volatile(
                            "mma.sync.aligned.m16n8k16.row.col.f32.f16.f16.f32 "
                            "{%0,%1,%2,%3}, {%4,%5,%6,%7}, {%8,%9}, {%0,%1,%2,%3};\n"
                            : "+f"(acc[mt][nt][0]), "+f"(acc[mt][nt][1]),
                              "+f"(acc[mt][nt][2]), "+f"(acc[mt][nt][3])
                            : "r"(a[mt][0]), "r"(a[mt][1]), "r"(a[mt][2]), "r"(a[mt][3]),
                              "r"(b[h * 2]), "r"(b[h * 2 + 1]));
                    }
                }
            }
        }

        // ---- stage A tile kt+1 ----
        if (kt + 1 < NKT) {
            #pragma unroll
            for (int j = 0; j < 2; ++j) {
                float4 xv = j ? xv1 : xv0;
                int e = tid + j * NTHREADS;
                int r = e >> 2;
                int grp = e & 3;
                float t0 = tanh_fast(xv.x), t1 = tanh_fast(xv.y);
                float t2 = tanh_fast(xv.z), t3 = tanh_fast(xv.w);
                float s0 = t0*t0, s1 = t1*t1, s2 = t2*t2, s3 = t3*t3;
                uint4 c01, c23;
                c01.x = pack_h2(t0, s0); c01.y = pack_h2(s0*t0, s0*s0);
                c01.z = pack_h2(t1, s1); c01.w = pack_h2(s1*t1, s1*s1);
                c23.x = pack_h2(t2, s2); c23.y = pack_h2(s2*t2, s2*s2);
                c23.z = pack_h2(t3, s3); c23.w = pack_h2(s3*t3, s3*s3);
                uint32_t off = (uint32_t)r * (SA * 2) + (uint32_t)grp * 32;
                *(uint4*)((char*)smem + (Abn - sbase) + off)      = c01;
                *(uint4*)((char*)smem + (Abn - sbase) + off + 16) = c23;
            }
        }
    }

    // ---- epilogue: + bias, fp32 store ----
    #pragma unroll
    for (int mt = 0; mt < 2; ++mt) {
        int r0 = rowbase + wr * 32 + mt * 16;
        #pragma unroll
        for (int nt = 0; nt < 8; ++nt) {
            int c0 = colbase + wc * 64 + nt * 8 + tig * 2;
            float b0 = __ldg(&g_bias[c0]);
            float b1 = __ldg(&g_bias[c0 + 1]);
            int r = r0 + g;
            float2 lo = make_float2(acc[mt][nt][0] + b0, acc[mt][nt][1] + b1);
            float2 hi = make_float2(acc[mt][nt][2] + b0, acc[mt][nt][3] + b1);
            *(float2*)(Y + (size_t)r * OUT_DIM + c0)       = lo;
            *(float2*)(Y + (size_t)(r + 8) * OUT_DIM + c0) = hi;
        }
    }
}

// ---------------------------------------------------------------------------
extern "C" void kernel_launch(void* const* d_in, const int* in_sizes, int n_in,
                              void* d_out, int out_size) {
    const float* x = (const float*)d_in[0];
    const float* coeffs = (const float*)d_in[1];
    if (n_in >= 2 && in_sizes[0] == OUT_DIM * IN_DIM * 6) {
        coeffs = (const float*)d_in[0];
        x = (const float*)d_in[1];
    }
    float* y = (float*)d_out;

    static bool attr_set = false;
    if (!attr_set) {
        cudaFuncSetAttribute(kan_gemm_kernel,
                             cudaFuncAttributeMaxDynamicSharedMemorySize, SM_TOTAL);
        attr_set = true;
    }

    prep_weights_kernel<<<OUT_DIM, IN_DIM>>>(coeffs);
    kan_gemm_kernel<<<(B_ROWS / BM) * (OUT_DIM / BN), NTHREADS, SM_TOTAL>>>(x, y);
}